// round 1
// baseline (speedup 1.0000x reference)
#include <cuda_runtime.h>
#include <math.h>
#include <stdint.h>

// CGGRLoss: one streaming pass over logits computes per-row online-softmax
// stats; a single-block finalize kernel does the global reductions, exact
// k-th-largest selection (bitonic sort, tie semantics match reference), and
// the masked-mean CE.

#define MAXN 8192

static __device__ float g_ce[MAXN];
static __device__ float g_conf[MAXN];
static __device__ float g_part[MAXN];   // ent_norm + 1 - margin
static __device__ float g_diff[MAXN];

// ---------------------------------------------------------------------------
// Online softmax state merge: (m1,m2,s,t) where s = sum exp(l - m1),
// t = sum exp(l - m1) * l, m1/m2 = top-2 values seen.
// ---------------------------------------------------------------------------
__device__ __forceinline__ void os_merge(float& m1, float& m2, float& s, float& t,
                                         float om1, float om2, float os, float ot) {
    float M1 = fmaxf(m1, om1);
    float M2 = fmaxf(fminf(m1, om1), fmaxf(m2, om2));
    float sa = (m1  == -INFINITY) ? 0.f : __expf(m1  - M1);
    float sb = (om1 == -INFINITY) ? 0.f : __expf(om1 - M1);
    s = s * sa + os * sb;
    t = t * sa + ot * sb;
    m1 = M1; m2 = M2;
}

__device__ __forceinline__ void os_accum(float& m1, float& m2, float& s, float& t, float x) {
    if (x > m1) {
        float sc = __expf(m1 - x);      // exp(-inf) == 0 handles the init case
        s = s * sc + 1.f;
        t = t * sc + x;
        m2 = m1;
        m1 = x;
    } else {
        float e = __expf(x - m1);
        s += e;
        t = fmaf(e, x, t);
        m2 = fmaxf(m2, x);
    }
}

// ---------------------------------------------------------------------------
// Kernel 1: one block per row. Streams V logits with float4 loads, produces
// ce, confidence (=p1), and part = ent_norm + 1 - margin per row.
// ---------------------------------------------------------------------------
__global__ void __launch_bounds__(256) row_stats_kernel(
    const float* __restrict__ lf, const int* __restrict__ tf,
    int V, float inv_logV)
{
    int row = blockIdx.x;
    const float* p = lf + (size_t)row * (size_t)V;

    float m1 = -INFINITY, m2 = -INFINITY, s = 0.f, t = 0.f;

    bool vec_ok = ((V & 3) == 0) && ((((uintptr_t)p) & 15u) == 0);
    if (vec_ok) {
        int V4 = V >> 2;
        const float4* p4 = reinterpret_cast<const float4*>(p);
        for (int i = threadIdx.x; i < V4; i += 256) {
            float4 v = p4[i];
            os_accum(m1, m2, s, t, v.x);
            os_accum(m1, m2, s, t, v.y);
            os_accum(m1, m2, s, t, v.z);
            os_accum(m1, m2, s, t, v.w);
        }
    } else {
        for (int i = threadIdx.x; i < V; i += 256) {
            os_accum(m1, m2, s, t, p[i]);
        }
    }

    // intra-warp butterfly reduce
    #pragma unroll
    for (int off = 16; off; off >>= 1) {
        float om1 = __shfl_xor_sync(0xffffffffu, m1, off);
        float om2 = __shfl_xor_sync(0xffffffffu, m2, off);
        float os  = __shfl_xor_sync(0xffffffffu, s,  off);
        float ot  = __shfl_xor_sync(0xffffffffu, t,  off);
        os_merge(m1, m2, s, t, om1, om2, os, ot);
    }

    __shared__ float sm1[8], sm2[8], ss[8], st[8];
    int wid = threadIdx.x >> 5;
    if ((threadIdx.x & 31) == 0) { sm1[wid] = m1; sm2[wid] = m2; ss[wid] = s; st[wid] = t; }
    __syncthreads();

    if (threadIdx.x == 0) {
        #pragma unroll
        for (int w = 1; w < 8; w++)
            os_merge(m1, m2, s, t, sm1[w], sm2[w], ss[w], st[w]);

        float logs = __logf(s);
        float logZ = m1 + logs;
        int   tgt  = tf[row];
        float lt   = __ldg(p + tgt);
        float ce   = logZ - lt;              // -log p(target)
        float ent  = logZ - t / s;           // -sum p log p
        float conf = 1.f / s;                // p1 = exp(m1 - logZ)
        float p2   = __expf(m2 - m1) * conf; // p2
        float margin = conf - p2;

        g_ce[row]   = ce;
        g_conf[row] = conf;
        g_part[row] = ent * inv_logV + 1.f - margin;
    }
}

// ---------------------------------------------------------------------------
// Block-wide reductions (1024 threads)
// ---------------------------------------------------------------------------
__device__ __forceinline__ float block_reduce_max(float v, float* rbuf) {
    #pragma unroll
    for (int off = 16; off; off >>= 1)
        v = fmaxf(v, __shfl_xor_sync(0xffffffffu, v, off));
    int w = threadIdx.x >> 5;
    if ((threadIdx.x & 31) == 0) rbuf[w] = v;
    __syncthreads();
    if (threadIdx.x < 32) {
        v = (threadIdx.x < (blockDim.x >> 5)) ? rbuf[threadIdx.x] : -INFINITY;
        #pragma unroll
        for (int off = 16; off; off >>= 1)
            v = fmaxf(v, __shfl_xor_sync(0xffffffffu, v, off));
        if (threadIdx.x == 0) rbuf[0] = v;
    }
    __syncthreads();
    float r = rbuf[0];
    __syncthreads();
    return r;
}

__device__ __forceinline__ float block_reduce_sum(float v, float* rbuf) {
    #pragma unroll
    for (int off = 16; off; off >>= 1)
        v += __shfl_xor_sync(0xffffffffu, v, off);
    int w = threadIdx.x >> 5;
    if ((threadIdx.x & 31) == 0) rbuf[w] = v;
    __syncthreads();
    if (threadIdx.x < 32) {
        v = (threadIdx.x < (blockDim.x >> 5)) ? rbuf[threadIdx.x] : 0.f;
        #pragma unroll
        for (int off = 16; off; off >>= 1)
            v += __shfl_xor_sync(0xffffffffu, v, off);
        if (threadIdx.x == 0) rbuf[0] = v;
    }
    __syncthreads();
    float r = rbuf[0];
    __syncthreads();
    return r;
}

// ---------------------------------------------------------------------------
// Kernel 2: single block. Global reductions -> difficulty -> exact k-th
// largest via bitonic sort in smem -> masked mean CE.
// ---------------------------------------------------------------------------
__global__ void __launch_bounds__(1024) finalize_kernel(
    const int* __restrict__ step_ptr, float* __restrict__ out, int N, int P)
{
    __shared__ float sd[MAXN];
    __shared__ float rbuf[32];
    int tid = threadIdx.x;
    int nt  = blockDim.x;

    // max(ce), sum(conf)
    float mce = -INFINITY, sconf = 0.f;
    for (int i = tid; i < N; i += nt) {
        mce = fmaxf(mce, g_ce[i]);
        sconf += g_conf[i];
    }
    float maxce   = block_reduce_max(mce, rbuf);
    float sumconf = block_reduce_sum(sconf, rbuf);

    // difficulty
    float invm = 1.f / (maxce + 1e-6f);
    for (int i = tid; i < N; i += nt) {
        float d = (g_part[i] + g_ce[i] * invm) * (1.f / 3.f);
        g_diff[i] = d;
        sd[i] = d;
    }
    for (int i = N + tid; i < P; i += nt) sd[i] = -INFINITY;  // pad low
    __syncthreads();

    // k from dynamic threshold ratio
    int   step      = *step_ptr;
    float progress  = fminf(1.f, (float)step * (1.f / 1000.f));
    float base_rat  = 1.f - progress * (1.f - 0.25f);
    float avg_conf  = sumconf / (float)N;
    float ratio     = base_rat * (1.f + 0.5f * (0.5f - avg_conf) * 2.f);
    ratio = fminf(fmaxf(ratio, 0.01f), 1.f);
    int k = (int)rintf(ratio * (float)N);   // round-half-even, matches jnp.round
    k = min(max(k, 1), N);

    // bitonic sort ascending over P (pads are -inf -> land at front)
    for (int kk = 2; kk <= P; kk <<= 1) {
        for (int j = kk >> 1; j > 0; j >>= 1) {
            for (int i = tid; i < P; i += nt) {
                int ixj = i ^ j;
                if (ixj > i) {
                    float a = sd[i], b = sd[ixj];
                    bool up = ((i & kk) == 0);
                    if ((a > b) == up) { sd[i] = b; sd[ixj] = a; }
                }
            }
            __syncthreads();
        }
    }
    float thr = sd[P - k];   // k-th largest of the N real values

    // masked mean CE
    float sce = 0.f, cnt = 0.f;
    for (int i = tid; i < N; i += nt) {
        if (g_diff[i] >= thr) { sce += g_ce[i]; cnt += 1.f; }
    }
    sce = block_reduce_sum(sce, rbuf);
    cnt = block_reduce_sum(cnt, rbuf);
    if (tid == 0) out[0] = sce / fmaxf(cnt, 1.f);
}

// ---------------------------------------------------------------------------
extern "C" void kernel_launch(void* const* d_in, const int* in_sizes, int n_in,
                              void* d_out, int out_size) {
    const float* lf   = (const float*)d_in[0];   // logits (B,S,V) fp32
    const int*   tf   = (const int*)d_in[1];     // targets (B,S) int32
    const int*   step = (const int*)d_in[2];     // step_count scalar int32

    int N = in_sizes[1];                 // B*S = 8192
    int V = in_sizes[0] / N;             // 32000
    if (N > MAXN) N = MAXN;              // scratch capacity guard (fixed shapes)

    int P = 1;
    while (P < N) P <<= 1;               // 8192

    float inv_logV = 1.f / logf((float)V);

    row_stats_kernel<<<N, 256>>>(lf, tf, V, inv_logV);
    finalize_kernel<<<1, 1024>>>(step, (float*)d_out, N, P);
}

// round 2
// speedup vs baseline: 1.3913x; 1.3913x over previous
#include <cuda_runtime.h>
#include <math.h>
#include <stdint.h>

// CGGRLoss: streaming pass computes per-row online-softmax stats (ce, p1,
// ent_norm + 1 - margin); finalize does global reductions, exact k-th-largest
// via radix select on orderable u32 keys, and the masked-mean CE.

#define MAXN 8192

static __device__ float g_ce[MAXN];
static __device__ float g_conf[MAXN];
static __device__ float g_part[MAXN];   // ent_norm + 1 - margin

// ---------------------------------------------------------------------------
// Online softmax state: s = sum exp(l - m1), t = sum exp(l - m1) * l,
// m1/m2 = top-2 raw logits seen so far.
// ---------------------------------------------------------------------------
struct OS { float m1, m2, s, t; };

__device__ __forceinline__ void os_init(OS& o) {
    o.m1 = -INFINITY; o.m2 = -INFINITY; o.s = 0.f; o.t = 0.f;
}

__device__ __forceinline__ void os_acc(OS& o, float x) {
    if (x > o.m1) {
        float sc = __expf(o.m1 - x);     // exp(-inf)=0 handles init
        o.s = fmaf(o.s, sc, 1.f);
        o.t = fmaf(o.t, sc, x);
        o.m2 = o.m1;
        o.m1 = x;
    } else {
        float e = __expf(x - o.m1);
        o.s += e;
        o.t = fmaf(e, x, o.t);
        o.m2 = fmaxf(o.m2, x);
    }
}

__device__ __forceinline__ void os_acc4(OS& o, float4 v) {
    os_acc(o, v.x); os_acc(o, v.y); os_acc(o, v.z); os_acc(o, v.w);
}

__device__ __forceinline__ void os_merge(OS& a, const OS& b) {
    float M1 = fmaxf(a.m1, b.m1);
    float M2 = fmaxf(fminf(a.m1, b.m1), fmaxf(a.m2, b.m2));
    float sa = (a.m1 == -INFINITY) ? 0.f : __expf(a.m1 - M1);
    float sb = (b.m1 == -INFINITY) ? 0.f : __expf(b.m1 - M1);
    a.s = a.s * sa + b.s * sb;
    a.t = a.t * sa + b.t * sb;
    a.m1 = M1; a.m2 = M2;
}

// ---------------------------------------------------------------------------
// Kernel 1: one block per row, 256 threads. 4 independent accumulator states
// per thread, 4 front-batched float4 loads per iteration (MLP=4).
// ---------------------------------------------------------------------------
__global__ void __launch_bounds__(256) row_stats_kernel(
    const float* __restrict__ lf, const int* __restrict__ tf,
    int V, float inv_logV)
{
    const int row = blockIdx.x;
    const float* p = lf + (size_t)row * (size_t)V;
    const int tid = threadIdx.x;

    OS st0, st1, st2, st3;
    os_init(st0); os_init(st1); os_init(st2); os_init(st3);

    if (((V & 3) == 0) && ((((uintptr_t)p) & 15u) == 0)) {
        const int V4 = V >> 2;
        const float4* p4 = reinterpret_cast<const float4*>(p);
        int i = tid;
        // main loop: 4 float4s per iteration, loads batched up front
        for (; i + 768 < V4; i += 1024) {
            float4 a = __ldcs(p4 + i);
            float4 b = __ldcs(p4 + i + 256);
            float4 c = __ldcs(p4 + i + 512);
            float4 d = __ldcs(p4 + i + 768);
            os_acc4(st0, a);
            os_acc4(st1, b);
            os_acc4(st2, c);
            os_acc4(st3, d);
        }
        for (; i < V4; i += 256) {
            float4 a = __ldcs(p4 + i);
            os_acc4(st0, a);
        }
    } else {
        for (int i = tid; i < V; i += 256) os_acc(st0, p[i]);
    }

    os_merge(st0, st1);
    os_merge(st2, st3);
    os_merge(st0, st2);

    // intra-warp butterfly merge
    #pragma unroll
    for (int off = 16; off; off >>= 1) {
        OS o;
        o.m1 = __shfl_xor_sync(0xffffffffu, st0.m1, off);
        o.m2 = __shfl_xor_sync(0xffffffffu, st0.m2, off);
        o.s  = __shfl_xor_sync(0xffffffffu, st0.s,  off);
        o.t  = __shfl_xor_sync(0xffffffffu, st0.t,  off);
        os_merge(st0, o);
    }

    __shared__ OS swarp[8];
    int wid = tid >> 5;
    if ((tid & 31) == 0) swarp[wid] = st0;
    __syncthreads();

    if (tid == 0) {
        #pragma unroll
        for (int w = 1; w < 8; w++) os_merge(st0, swarp[w]);

        float logs = __logf(st0.s);
        float logZ = st0.m1 + logs;
        int   tgt  = tf[row];
        float lt   = __ldg(p + tgt);
        float ce   = logZ - lt;                    // -log p(target)
        float ent  = logZ - st0.t / st0.s;         // entropy
        float conf = 1.f / st0.s;                  // top-1 prob
        float p2   = __expf(st0.m2 - st0.m1) * conf;
        float margin = conf - p2;

        g_ce[row]   = ce;
        g_conf[row] = conf;
        g_part[row] = ent * inv_logV + 1.f - margin;
    }
}

// ---------------------------------------------------------------------------
// Block reductions (1024 threads)
// ---------------------------------------------------------------------------
__device__ __forceinline__ float block_reduce_max(float v, float* rbuf) {
    #pragma unroll
    for (int off = 16; off; off >>= 1)
        v = fmaxf(v, __shfl_xor_sync(0xffffffffu, v, off));
    int w = threadIdx.x >> 5;
    if ((threadIdx.x & 31) == 0) rbuf[w] = v;
    __syncthreads();
    if (threadIdx.x < 32) {
        v = (threadIdx.x < (blockDim.x >> 5)) ? rbuf[threadIdx.x] : -INFINITY;
        #pragma unroll
        for (int off = 16; off; off >>= 1)
            v = fmaxf(v, __shfl_xor_sync(0xffffffffu, v, off));
        if (threadIdx.x == 0) rbuf[0] = v;
    }
    __syncthreads();
    float r = rbuf[0];
    __syncthreads();
    return r;
}

__device__ __forceinline__ float block_reduce_sum(float v, float* rbuf) {
    #pragma unroll
    for (int off = 16; off; off >>= 1)
        v += __shfl_xor_sync(0xffffffffu, v, off);
    int w = threadIdx.x >> 5;
    if ((threadIdx.x & 31) == 0) rbuf[w] = v;
    __syncthreads();
    if (threadIdx.x < 32) {
        v = (threadIdx.x < (blockDim.x >> 5)) ? rbuf[threadIdx.x] : 0.f;
        #pragma unroll
        for (int off = 16; off; off >>= 1)
            v += __shfl_xor_sync(0xffffffffu, v, off);
        if (threadIdx.x == 0) rbuf[0] = v;
    }
    __syncthreads();
    float r = rbuf[0];
    __syncthreads();
    return r;
}

// order-preserving float->u32 map (ascending float == ascending uint)
__device__ __forceinline__ unsigned f2key(float f) {
    unsigned u = __float_as_uint(f);
    return (u & 0x80000000u) ? ~u : (u | 0x80000000u);
}

// ---------------------------------------------------------------------------
// Kernel 2: single block, 1024 threads. Reductions -> difficulty keys ->
// exact k-th-largest via 4-pass 8-bit radix select -> masked mean CE.
// ---------------------------------------------------------------------------
__global__ void __launch_bounds__(1024) finalize_kernel(
    const int* __restrict__ step_ptr, float* __restrict__ out, int N)
{
    __shared__ unsigned skey[MAXN];
    __shared__ unsigned hist[256];
    __shared__ float rbuf[32];
    __shared__ unsigned s_prefix;
    __shared__ int s_rank;

    const int tid = threadIdx.x;
    const int nt  = blockDim.x;

    // reductions: max(ce), sum(conf)
    float mce = -INFINITY, sconf = 0.f;
    for (int i = tid; i < N; i += nt) {
        mce = fmaxf(mce, g_ce[i]);
        sconf += g_conf[i];
    }
    float maxce   = block_reduce_max(mce, rbuf);
    float sumconf = block_reduce_sum(sconf, rbuf);

    // difficulty keys
    float invm = 1.f / (maxce + 1e-6f);
    for (int i = tid; i < N; i += nt) {
        float d = (g_part[i] + g_ce[i] * invm) * (1.f / 3.f);
        skey[i] = f2key(d);
    }

    // k from dynamic threshold ratio
    int   step      = *step_ptr;
    float progress  = fminf(1.f, (float)step * (1.f / 1000.f));
    float base_rat  = 1.f - progress * (1.f - 0.25f);
    float avg_conf  = sumconf / (float)N;
    float ratio     = base_rat * (1.f + 0.5f * (0.5f - avg_conf) * 2.f);
    ratio = fminf(fmaxf(ratio, 0.01f), 1.f);
    int k = (int)rintf(ratio * (float)N);   // round-half-even == jnp.round
    k = min(max(k, 1), N);

    if (tid == 0) { s_prefix = 0u; s_rank = k; }

    // 4-pass radix select: find k-th largest key exactly
    #pragma unroll
    for (int pass = 0; pass < 4; pass++) {
        const int shift = 24 - pass * 8;
        const unsigned himask = (pass == 0) ? 0u : (0xFFFFFFFFu << (32 - pass * 8));
        if (tid < 256) hist[tid] = 0u;
        __syncthreads();
        unsigned prefix = s_prefix;
        for (int i = tid; i < N; i += nt) {
            unsigned key = skey[i];
            if ((key & himask) == prefix)
                atomicAdd(&hist[(key >> shift) & 255u], 1u);
        }
        __syncthreads();
        if (tid == 0) {
            int r = s_rank;
            int cum = 0;
            int d = 255;
            for (; d >= 0; d--) {
                int c = (int)hist[d];
                if (cum + c >= r) { s_rank = r - cum; break; }
                cum += c;
            }
            s_prefix = prefix | ((unsigned)d << shift);
        }
        __syncthreads();
    }
    unsigned thr_key = s_prefix;   // exact k-th largest difficulty (as key)

    // masked mean CE: (key >= thr_key) <=> (difficulty >= threshold)
    float sce = 0.f, cnt = 0.f;
    for (int i = tid; i < N; i += nt) {
        if (skey[i] >= thr_key) { sce += g_ce[i]; cnt += 1.f; }
    }
    sce = block_reduce_sum(sce, rbuf);
    cnt = block_reduce_sum(cnt, rbuf);
    if (tid == 0) out[0] = sce / fmaxf(cnt, 1.f);
}

// ---------------------------------------------------------------------------
extern "C" void kernel_launch(void* const* d_in, const int* in_sizes, int n_in,
                              void* d_out, int out_size) {
    const float* lf   = (const float*)d_in[0];   // logits (B,S,V) fp32
    const int*   tf   = (const int*)d_in[1];     // targets (B,S) int32
    const int*   step = (const int*)d_in[2];     // step_count scalar int32

    int N = in_sizes[1];                 // B*S = 8192
    int V = in_sizes[0] / N;             // 32000
    if (N > MAXN) N = MAXN;

    float inv_logV = 1.f / logf((float)V);

    row_stats_kernel<<<N, 256>>>(lf, tf, V, inv_logV);
    finalize_kernel<<<1, 1024>>>(step, (float*)d_out, N);
}

// round 3
// speedup vs baseline: 1.5461x; 1.1113x over previous
#include <cuda_runtime.h>
#include <math.h>
#include <stdint.h>

// CGGRLoss fused: grid of row blocks computes per-row online-softmax stats
// (ce, p1, ent_norm + 1 - margin); the last block to finish runs the global
// finalize: reductions, exact k-th-largest via warp-aggregated radix select,
// masked-mean CE.

#define MAXN 8192

static __device__ float g_ce[MAXN];
static __device__ float g_conf[MAXN];
static __device__ float g_part[MAXN];   // ent_norm + 1 - margin
static __device__ unsigned g_done;      // zero-initialized; reset in-kernel

// ---------------------------------------------------------------------------
// Online softmax state: s = sum exp(l - m1), t = sum exp(l - m1) * l,
// m1/m2 = top-2 raw logits. Branchless accumulate: exactly one MUFU per elem.
// ---------------------------------------------------------------------------
struct OS { float m1, m2, s, t; };

__device__ __forceinline__ void os_init(OS& o) {
    o.m1 = -INFINITY; o.m2 = -INFINITY; o.s = 0.f; o.t = 0.f;
}

__device__ __forceinline__ void os_acc(OS& o, float x) {
    float lo = fminf(x, o.m1);
    float hi = fmaxf(x, o.m1);
    float w  = __expf(lo - hi);          // exp(-|x-m1|); exp(-inf)=0 at init
    bool  up = x > o.m1;
    float sc = up ? w : 1.f;             // rescale of old sums
    float e  = up ? 1.f : w;             // this element's exp weight
    o.s  = fmaf(o.s, sc, e);
    o.t  = fmaf(o.t, sc, e * x);
    o.m2 = fmaxf(o.m2, lo);
    o.m1 = hi;
}

__device__ __forceinline__ void os_acc4(OS& o, float4 v) {
    os_acc(o, v.x); os_acc(o, v.y); os_acc(o, v.z); os_acc(o, v.w);
}

__device__ __forceinline__ void os_merge(OS& a, const OS& b) {
    float M1 = fmaxf(a.m1, b.m1);
    float M2 = fmaxf(fminf(a.m1, b.m1), fmaxf(a.m2, b.m2));
    float sa = (a.m1 == -INFINITY) ? 0.f : __expf(a.m1 - M1);
    float sb = (b.m1 == -INFINITY) ? 0.f : __expf(b.m1 - M1);
    a.s = a.s * sa + b.s * sb;
    a.t = a.t * sa + b.t * sb;
    a.m1 = M1; a.m2 = M2;
}

// ---------------------------------------------------------------------------
// Block reductions for 256 threads (8 warps)
// ---------------------------------------------------------------------------
__device__ __forceinline__ float blk_max(float v, float* rbuf) {
    #pragma unroll
    for (int off = 16; off; off >>= 1)
        v = fmaxf(v, __shfl_xor_sync(0xffffffffu, v, off));
    int w = threadIdx.x >> 5;
    if ((threadIdx.x & 31) == 0) rbuf[w] = v;
    __syncthreads();
    if (threadIdx.x < 8) {
        v = rbuf[threadIdx.x];
        #pragma unroll
        for (int off = 4; off; off >>= 1)
            v = fmaxf(v, __shfl_xor_sync(0xffu, v, off));
        if (threadIdx.x == 0) rbuf[0] = v;
    }
    __syncthreads();
    float r = rbuf[0];
    __syncthreads();
    return r;
}

__device__ __forceinline__ float blk_sum(float v, float* rbuf) {
    #pragma unroll
    for (int off = 16; off; off >>= 1)
        v += __shfl_xor_sync(0xffffffffu, v, off);
    int w = threadIdx.x >> 5;
    if ((threadIdx.x & 31) == 0) rbuf[w] = v;
    __syncthreads();
    if (threadIdx.x < 8) {
        v = rbuf[threadIdx.x];
        #pragma unroll
        for (int off = 4; off; off >>= 1)
            v += __shfl_xor_sync(0xffu, v, off);
        if (threadIdx.x == 0) rbuf[0] = v;
    }
    __syncthreads();
    float r = rbuf[0];
    __syncthreads();
    return r;
}

// order-preserving float->u32 map
__device__ __forceinline__ unsigned f2key(float f) {
    unsigned u = __float_as_uint(f);
    return (u & 0x80000000u) ? ~u : (u | 0x80000000u);
}

// ---------------------------------------------------------------------------
// Fused kernel: one block per row (256 threads); last block finalizes.
// ---------------------------------------------------------------------------
__global__ void __launch_bounds__(256) cggr_kernel(
    const float* __restrict__ lf, const int* __restrict__ tf,
    const int* __restrict__ step_ptr, float* __restrict__ out,
    int V, int N, float inv_logV)
{
    const int row = blockIdx.x;
    const int tid = threadIdx.x;
    const int lane = tid & 31;
    const float* p = lf + (size_t)row * (size_t)V;

    __shared__ float rbuf[8];
    __shared__ OS swarp[8];
    __shared__ unsigned skey[MAXN];      // 32 KB: radix-select keys
    __shared__ unsigned hist[256];
    __shared__ unsigned suf[257];
    __shared__ unsigned s_prefix;
    __shared__ int s_rank;
    __shared__ int s_last;

    // ---- phase 1: per-row online softmax stats ----
    OS st0, st1, st2, st3;
    os_init(st0); os_init(st1); os_init(st2); os_init(st3);

    if (((V & 3) == 0) && ((((uintptr_t)p) & 15u) == 0)) {
        const int V4 = V >> 2;
        const float4* p4 = reinterpret_cast<const float4*>(p);
        int i = tid;
        for (; i + 768 < V4; i += 1024) {
            float4 a = __ldcs(p4 + i);
            float4 b = __ldcs(p4 + i + 256);
            float4 c = __ldcs(p4 + i + 512);
            float4 d = __ldcs(p4 + i + 768);
            os_acc4(st0, a);
            os_acc4(st1, b);
            os_acc4(st2, c);
            os_acc4(st3, d);
        }
        for (; i < V4; i += 256) {
            float4 a = __ldcs(p4 + i);
            os_acc4(st0, a);
        }
    } else {
        for (int i = tid; i < V; i += 256) os_acc(st0, p[i]);
    }

    os_merge(st0, st1);
    os_merge(st2, st3);
    os_merge(st0, st2);

    #pragma unroll
    for (int off = 16; off; off >>= 1) {
        OS o;
        o.m1 = __shfl_xor_sync(0xffffffffu, st0.m1, off);
        o.m2 = __shfl_xor_sync(0xffffffffu, st0.m2, off);
        o.s  = __shfl_xor_sync(0xffffffffu, st0.s,  off);
        o.t  = __shfl_xor_sync(0xffffffffu, st0.t,  off);
        os_merge(st0, o);
    }
    if (lane == 0) swarp[tid >> 5] = st0;
    __syncthreads();

    if (tid == 0) {
        #pragma unroll
        for (int w = 1; w < 8; w++) os_merge(st0, swarp[w]);

        float logs = __logf(st0.s);
        float logZ = st0.m1 + logs;
        int   tgt  = tf[row];
        float lt   = __ldg(p + tgt);
        float ce   = logZ - lt;
        float ent  = logZ - st0.t / st0.s;
        float conf = 1.f / st0.s;                    // p1
        float p2   = __expf(st0.m2 - st0.m1) * conf;
        float margin = conf - p2;

        g_ce[row]   = ce;
        g_conf[row] = conf;
        g_part[row] = ent * inv_logV + 1.f - margin;

        __threadfence();                             // release stats
        unsigned prev = atomicAdd(&g_done, 1u);
        s_last = (prev == (unsigned)(N - 1)) ? 1 : 0;
    }
    __syncthreads();
    if (!s_last) return;

    // ---- phase 2: finalize (single surviving block, 256 threads) ----
    __threadfence();                                 // acquire other blocks' stats

    // reductions: max(ce), sum(conf)
    float mce = -INFINITY, sconf = 0.f;
    for (int i = tid; i < N; i += 256) {
        mce = fmaxf(mce, __ldcg(&g_ce[i]));
        sconf += __ldcg(&g_conf[i]);
    }
    float maxce   = blk_max(mce, rbuf);
    float sumconf = blk_sum(sconf, rbuf);

    // difficulty keys into smem
    float invm = 1.f / (maxce + 1e-6f);
    for (int i = tid; i < N; i += 256) {
        float d = (__ldcg(&g_part[i]) + __ldcg(&g_ce[i]) * invm) * (1.f / 3.f);
        skey[i] = f2key(d);
    }

    // k from dynamic threshold ratio
    if (tid == 0) {
        int   step     = *step_ptr;
        float progress = fminf(1.f, (float)step * (1.f / 1000.f));
        float base_rat = 1.f - progress * (1.f - 0.25f);
        float avg_conf = sumconf / (float)N;
        float ratio    = base_rat * (1.f + 0.5f * (0.5f - avg_conf) * 2.f);
        ratio = fminf(fmaxf(ratio, 0.01f), 1.f);
        int k = (int)rintf(ratio * (float)N);        // round-half-even == jnp.round
        k = min(max(k, 1), N);
        s_rank = k;
        s_prefix = 0u;
    }
    __syncthreads();

    const int Npad = (N + 255) & ~255;

    // 4-pass radix select for exact k-th largest key
    #pragma unroll
    for (int pass = 0; pass < 4; pass++) {
        const int shift = 24 - pass * 8;
        const unsigned himask = (pass == 0) ? 0u : (0xFFFFFFFFu << (32 - pass * 8));
        if (tid < 256) hist[tid] = 0u;
        __syncthreads();
        unsigned prefix = s_prefix;

        // warp-aggregated histogram (match_any collapses identical digits)
        for (int i = tid; i < Npad; i += 256) {
            int digit = -1;
            if (i < N) {
                unsigned key = skey[i];
                if ((key & himask) == prefix) digit = (int)((key >> shift) & 255u);
            }
            unsigned m = __match_any_sync(0xffffffffu, digit);
            int leader = __ffs(m) - 1;
            if (lane == leader && digit >= 0)
                atomicAdd(&hist[digit], (unsigned)__popc(m));
        }
        __syncthreads();

        // parallel suffix sum: suf[d] = sum_{j>=d} hist[j]
        if (tid < 256) suf[tid] = hist[tid];
        __syncthreads();
        #pragma unroll
        for (int off = 1; off < 256; off <<= 1) {
            unsigned add = (tid < 256 && tid + off < 256) ? suf[tid + off] : 0u;
            __syncthreads();
            if (tid < 256) suf[tid] += add;
            __syncthreads();
        }

        // unique winner digit: largest d with suf[d] >= rank
        int r = s_rank;
        if (tid < 256) {
            unsigned here = suf[tid];
            unsigned above = (tid == 255) ? 0u : suf[tid + 1];
            if ((int)here >= r && (int)above < r) {
                s_prefix = prefix | ((unsigned)tid << shift);
                s_rank = r - (int)above;
            }
        }
        __syncthreads();
    }
    unsigned thr_key = s_prefix;    // exact k-th largest difficulty key

    // masked mean CE: (key >= thr_key) <=> (difficulty >= threshold)
    float sce = 0.f, cnt = 0.f;
    for (int i = tid; i < N; i += 256) {
        if (skey[i] >= thr_key) { sce += __ldcg(&g_ce[i]); cnt += 1.f; }
    }
    sce = blk_sum(sce, rbuf);
    cnt = blk_sum(cnt, rbuf);
    if (tid == 0) {
        out[0] = sce / fmaxf(cnt, 1.f);
        g_done = 0;                 // reset for next graph replay
    }
}

// ---------------------------------------------------------------------------
extern "C" void kernel_launch(void* const* d_in, const int* in_sizes, int n_in,
                              void* d_out, int out_size) {
    const float* lf   = (const float*)d_in[0];   // logits (B,S,V) fp32
    const int*   tf   = (const int*)d_in[1];     // targets (B,S) int32
    const int*   step = (const int*)d_in[2];     // step_count scalar int32

    int N = in_sizes[1];                 // B*S = 8192
    int V = in_sizes[0] / N;             // 32000
    if (N > MAXN) N = MAXN;

    float inv_logV = 1.f / logf((float)V);

    cggr_kernel<<<N, 256>>>(lf, tf, step, (float*)d_out, V, N, inv_logV);
}

// round 4
// speedup vs baseline: 1.5644x; 1.0119x over previous
#include <cuda_runtime.h>
#include <math.h>
#include <stdint.h>

// CGGRLoss fused: one block per row computes online-softmax stats with a
// lazily-rescaled exp base (exact top-2 tracked separately); the last block
// finalizes: global reductions, exact k-th-largest via warp-aggregated radix
// select, masked-mean CE.

#define MAXN 8192
#define LOG2E 1.4426950408889634f

static __device__ float g_ce[MAXN];
static __device__ float g_conf[MAXN];
static __device__ float g_part[MAXN];     // ent_norm + 1 - margin
static __device__ unsigned g_key[MAXN];   // finalize scratch (radix keys)
static __device__ unsigned g_done;        // zero-init; reset in-kernel

__device__ __forceinline__ float ex2f(float x) {
    float y;
    asm("ex2.approx.ftz.f32 %0, %1;" : "=f"(y) : "f"(x));
    return y;   // ex2(-inf) = +0, ex2(0) = 1 exactly
}

// merge state used only in cold reduction paths
struct OS { float m1, m2, s, t; };

__device__ __forceinline__ void os_merge(OS& a, const OS& b) {
    float M1 = fmaxf(a.m1, b.m1);
    float M2 = fmaxf(fminf(a.m1, b.m1), fmaxf(a.m2, b.m2));
    float sa = (a.m1 == -INFINITY) ? 0.f : __expf(a.m1 - M1);
    float sb = (b.m1 == -INFINITY) ? 0.f : __expf(b.m1 - M1);
    a.s = a.s * sa + b.s * sb;
    a.t = a.t * sa + b.t * sb;
    a.m1 = M1; a.m2 = M2;
}

__device__ __forceinline__ float blk_max(float v, float* rbuf) {
    #pragma unroll
    for (int off = 16; off; off >>= 1)
        v = fmaxf(v, __shfl_xor_sync(0xffffffffu, v, off));
    if ((threadIdx.x & 31) == 0) rbuf[threadIdx.x >> 5] = v;
    __syncthreads();
    if (threadIdx.x < 8) {
        v = rbuf[threadIdx.x];
        #pragma unroll
        for (int off = 4; off; off >>= 1)
            v = fmaxf(v, __shfl_xor_sync(0xffu, v, off));
        if (threadIdx.x == 0) rbuf[0] = v;
    }
    __syncthreads();
    float r = rbuf[0];
    __syncthreads();
    return r;
}

__device__ __forceinline__ float blk_sum(float v, float* rbuf) {
    #pragma unroll
    for (int off = 16; off; off >>= 1)
        v += __shfl_xor_sync(0xffffffffu, v, off);
    if ((threadIdx.x & 31) == 0) rbuf[threadIdx.x >> 5] = v;
    __syncthreads();
    if (threadIdx.x < 8) {
        v = rbuf[threadIdx.x];
        #pragma unroll
        for (int off = 4; off; off >>= 1)
            v += __shfl_xor_sync(0xffu, v, off);
        if (threadIdx.x == 0) rbuf[0] = v;
    }
    __syncthreads();
    float r = rbuf[0];
    __syncthreads();
    return r;
}

__device__ __forceinline__ unsigned f2key(float f) {
    unsigned u = __float_as_uint(f);
    return (u & 0x80000000u) ? ~u : (u | 0x80000000u);
}

// ---------------------------------------------------------------------------
__global__ void __launch_bounds__(256) cggr_kernel(
    const float* __restrict__ lf, const int* __restrict__ tf,
    const int* __restrict__ step_ptr, float* __restrict__ out,
    int V, int N, float inv_logV)
{
    const int row  = blockIdx.x;
    const int tid  = threadIdx.x;
    const int lane = tid & 31;
    const float* p = lf + (size_t)row * (size_t)V;

    __shared__ float rbuf[8];
    __shared__ OS swarp[8];
    __shared__ unsigned hist[256];
    __shared__ unsigned suf[257];
    __shared__ unsigned s_prefix;
    __shared__ int s_rank;
    __shared__ int s_last;
    __shared__ float s_lt;

    // prefetch target logit before the stream evicts the line
    if (tid == 0) s_lt = __ldg(p + __ldg(tf + row));

    // ---- phase 1: per-row streaming stats ----
    // top-2 tracked exactly in (m1, m2); exp accumulators (s0,s1,t0,t1) are
    // relative to base bm (kept == m1 after every group); b2 = bm * log2e.
    float m1 = -INFINITY, m2 = -INFINITY;
    float bm = -INFINITY, b2 = -INFINITY;
    float s0 = 0.f, s1 = 0.f, t0 = 0.f, t1 = 0.f;

    if (((V & 3) == 0) && ((((uintptr_t)p) & 15u) == 0)) {
        const int V4 = V >> 2;
        const float4* p4 = reinterpret_cast<const float4*>(p);
        int i = tid;
        float4 cur = __ldcs(p4 + i);           // V4 >> blockDim for this problem
        for (;;) {
            int nx = i + 256;
            bool has = nx < V4;
            float4 nxt;
            if (has) nxt = __ldcs(p4 + nx);    // prefetch next (MLP=2/thread)

            // exact top-2 over the group
            float lo;
            lo = fminf(cur.x, m1); m1 = fmaxf(cur.x, m1); m2 = fmaxf(m2, lo);
            lo = fminf(cur.y, m1); m1 = fmaxf(cur.y, m1); m2 = fmaxf(m2, lo);
            lo = fminf(cur.z, m1); m1 = fmaxf(cur.z, m1); m2 = fmaxf(m2, lo);
            lo = fminf(cur.w, m1); m1 = fmaxf(cur.w, m1); m2 = fmaxf(m2, lo);

            // lazy rescale: only when a new max appeared (rare after warmup)
            if (m1 > bm) {
                float nb2 = m1 * LOG2E;
                float sc  = ex2f(b2 - nb2);    // exp(old-new); 0 at first group
                s0 *= sc; s1 *= sc; t0 *= sc; t1 *= sc;
                bm = m1; b2 = nb2;
            }

            // e = exp(x - bm), guaranteed <= 1
            float e;
            e = ex2f(fmaf(cur.x, LOG2E, -b2)); s0 += e; t0 = fmaf(e, cur.x, t0);
            e = ex2f(fmaf(cur.y, LOG2E, -b2)); s1 += e; t1 = fmaf(e, cur.y, t1);
            e = ex2f(fmaf(cur.z, LOG2E, -b2)); s0 += e; t0 = fmaf(e, cur.z, t0);
            e = ex2f(fmaf(cur.w, LOG2E, -b2)); s1 += e; t1 = fmaf(e, cur.w, t1);

            if (!has) break;
            cur = nxt; i = nx;
        }
    } else {
        for (int i = tid; i < V; i += 256) {
            float x = p[i];
            float lo = fminf(x, m1); m1 = fmaxf(x, m1); m2 = fmaxf(m2, lo);
            if (m1 > bm) {
                float nb2 = m1 * LOG2E;
                float sc  = ex2f(b2 - nb2);
                s0 *= sc; s1 *= sc; t0 *= sc; t1 *= sc;
                bm = m1; b2 = nb2;
            }
            float e = ex2f(fmaf(x, LOG2E, -b2));
            s0 += e; t0 = fmaf(e, x, t0);
        }
    }

    OS st;
    st.m1 = m1; st.m2 = m2; st.s = s0 + s1; st.t = t0 + t1;

    #pragma unroll
    for (int off = 16; off; off >>= 1) {
        OS o;
        o.m1 = __shfl_xor_sync(0xffffffffu, st.m1, off);
        o.m2 = __shfl_xor_sync(0xffffffffu, st.m2, off);
        o.s  = __shfl_xor_sync(0xffffffffu, st.s,  off);
        o.t  = __shfl_xor_sync(0xffffffffu, st.t,  off);
        os_merge(st, o);
    }
    if (lane == 0) swarp[tid >> 5] = st;
    __syncthreads();

    if (tid == 0) {
        #pragma unroll
        for (int w = 1; w < 8; w++) os_merge(st, swarp[w]);

        float logs = __logf(st.s);
        float logZ = st.m1 + logs;
        float ce   = logZ - s_lt;
        float ent  = logZ - st.t / st.s;
        float conf = 1.f / st.s;                    // p1
        float p2   = __expf(st.m2 - st.m1) * conf;  // p2
        float margin = conf - p2;

        g_ce[row]   = ce;
        g_conf[row] = conf;
        g_part[row] = ent * inv_logV + 1.f - margin;

        __threadfence();
        unsigned prev = atomicAdd(&g_done, 1u);
        s_last = (prev == (unsigned)(N - 1)) ? 1 : 0;
    }
    __syncthreads();
    if (!s_last) return;

    // ---- phase 2: finalize (single surviving block) ----
    __threadfence();

    float mce = -INFINITY, sconf = 0.f;
    for (int i = tid; i < N; i += 256) {
        mce = fmaxf(mce, __ldcg(&g_ce[i]));
        sconf += __ldcg(&g_conf[i]);
    }
    float maxce   = blk_max(mce, rbuf);
    float sumconf = blk_sum(sconf, rbuf);

    float invm = 1.f / (maxce + 1e-6f);
    for (int i = tid; i < N; i += 256) {
        float d = (__ldcg(&g_part[i]) + __ldcg(&g_ce[i]) * invm) * (1.f / 3.f);
        g_key[i] = f2key(d);
    }

    if (tid == 0) {
        int   step     = *step_ptr;
        float progress = fminf(1.f, (float)step * (1.f / 1000.f));
        float base_rat = 1.f - progress * (1.f - 0.25f);
        float avg_conf = sumconf / (float)N;
        float ratio    = base_rat * (1.f + 0.5f * (0.5f - avg_conf) * 2.f);
        ratio = fminf(fmaxf(ratio, 0.01f), 1.f);
        int k = (int)rintf(ratio * (float)N);       // round-half-even == jnp.round
        k = min(max(k, 1), N);
        s_rank = k;
        s_prefix = 0u;
    }
    __syncthreads();

    const int Npad = (N + 255) & ~255;

    #pragma unroll
    for (int pass = 0; pass < 4; pass++) {
        const int shift = 24 - pass * 8;
        const unsigned himask = (pass == 0) ? 0u : (0xFFFFFFFFu << (32 - pass * 8));
        hist[tid] = 0u;
        __syncthreads();
        unsigned prefix = s_prefix;

        for (int i = tid; i < Npad; i += 256) {
            int digit = -1;
            if (i < N) {
                unsigned key = g_key[i];
                if ((key & himask) == prefix) digit = (int)((key >> shift) & 255u);
            }
            unsigned m = __match_any_sync(0xffffffffu, digit);
            int leader = __ffs(m) - 1;
            if (lane == leader && digit >= 0)
                atomicAdd(&hist[digit], (unsigned)__popc(m));
        }
        __syncthreads();

        suf[tid] = hist[tid];
        __syncthreads();
        #pragma unroll
        for (int off = 1; off < 256; off <<= 1) {
            unsigned add = (tid + off < 256) ? suf[tid + off] : 0u;
            __syncthreads();
            suf[tid] += add;
            __syncthreads();
        }

        int r = s_rank;
        unsigned here  = suf[tid];
        unsigned above = (tid == 255) ? 0u : suf[tid + 1];
        if ((int)here >= r && (int)above < r) {
            s_prefix = prefix | ((unsigned)tid << shift);
            s_rank = r - (int)above;
        }
        __syncthreads();
    }
    unsigned thr_key = s_prefix;   // exact k-th largest difficulty key

    float sce = 0.f, cnt = 0.f;
    for (int i = tid; i < N; i += 256) {
        if (g_key[i] >= thr_key) { sce += __ldcg(&g_ce[i]); cnt += 1.f; }
    }
    sce = blk_sum(sce, rbuf);
    cnt = blk_sum(cnt, rbuf);
    if (tid == 0) {
        out[0] = sce / fmaxf(cnt, 1.f);
        g_done = 0;               // reset for next graph replay
    }
}

// ---------------------------------------------------------------------------
extern "C" void kernel_launch(void* const* d_in, const int* in_sizes, int n_in,
                              void* d_out, int out_size) {
    const float* lf   = (const float*)d_in[0];   // logits (B,S,V) fp32
    const int*   tf   = (const int*)d_in[1];     // targets (B,S) int32
    const int*   step = (const int*)d_in[2];     // step_count scalar int32

    int N = in_sizes[1];                 // B*S = 8192
    int V = in_sizes[0] / N;             // 32000
    if (N > MAXN) N = MAXN;

    float inv_logV = 1.f / logf((float)V);

    cggr_kernel<<<N, 256>>>(lf, tf, step, (float*)d_out, V, N, inv_logV);
}

// round 5
// speedup vs baseline: 1.6609x; 1.0617x over previous
#include <cuda_runtime.h>
#include <math.h>
#include <stdint.h>

// CGGRLoss fused: one block per row computes online-softmax stats with a
// lazily-rescaled exp base (exact top-2 tracked separately); the last block
// finalizes: global reductions, exact k-th-largest via warp-aggregated radix
// select, masked-mean CE.
// R5: 2 float4/iter with cross-iteration prefetch of the next 2 (up to 4 LDG
// in flight per thread) to break the 32KB/SM in-flight plateau.

#define MAXN 8192
#define LOG2E 1.4426950408889634f

static __device__ float g_ce[MAXN];
static __device__ float g_conf[MAXN];
static __device__ float g_part[MAXN];     // ent_norm + 1 - margin
static __device__ unsigned g_key[MAXN];   // finalize scratch (radix keys)
static __device__ unsigned g_done;        // zero-init; reset in-kernel

__device__ __forceinline__ float ex2f(float x) {
    float y;
    asm("ex2.approx.ftz.f32 %0, %1;" : "=f"(y) : "f"(x));
    return y;   // ex2(-inf) = +0, ex2(0) = 1 exactly
}

struct OS { float m1, m2, s, t; };

__device__ __forceinline__ void os_merge(OS& a, const OS& b) {
    float M1 = fmaxf(a.m1, b.m1);
    float M2 = fmaxf(fminf(a.m1, b.m1), fmaxf(a.m2, b.m2));
    float sa = (a.m1 == -INFINITY) ? 0.f : __expf(a.m1 - M1);
    float sb = (b.m1 == -INFINITY) ? 0.f : __expf(b.m1 - M1);
    a.s = a.s * sa + b.s * sb;
    a.t = a.t * sa + b.t * sb;
    a.m1 = M1; a.m2 = M2;
}

__device__ __forceinline__ float blk_max(float v, float* rbuf) {
    #pragma unroll
    for (int off = 16; off; off >>= 1)
        v = fmaxf(v, __shfl_xor_sync(0xffffffffu, v, off));
    if ((threadIdx.x & 31) == 0) rbuf[threadIdx.x >> 5] = v;
    __syncthreads();
    if (threadIdx.x < 8) {
        v = rbuf[threadIdx.x];
        #pragma unroll
        for (int off = 4; off; off >>= 1)
            v = fmaxf(v, __shfl_xor_sync(0xffu, v, off));
        if (threadIdx.x == 0) rbuf[0] = v;
    }
    __syncthreads();
    float r = rbuf[0];
    __syncthreads();
    return r;
}

__device__ __forceinline__ float blk_sum(float v, float* rbuf) {
    #pragma unroll
    for (int off = 16; off; off >>= 1)
        v += __shfl_xor_sync(0xffffffffu, v, off);
    if ((threadIdx.x & 31) == 0) rbuf[threadIdx.x >> 5] = v;
    __syncthreads();
    if (threadIdx.x < 8) {
        v = rbuf[threadIdx.x];
        #pragma unroll
        for (int off = 4; off; off >>= 1)
            v += __shfl_xor_sync(0xffu, v, off);
        if (threadIdx.x == 0) rbuf[0] = v;
    }
    __syncthreads();
    float r = rbuf[0];
    __syncthreads();
    return r;
}

__device__ __forceinline__ unsigned f2key(float f) {
    unsigned u = __float_as_uint(f);
    return (u & 0x80000000u) ? ~u : (u | 0x80000000u);
}

// ---------------------------------------------------------------------------
__global__ void __launch_bounds__(256) cggr_kernel(
    const float* __restrict__ lf, const int* __restrict__ tf,
    const int* __restrict__ step_ptr, float* __restrict__ out,
    int V, int N, float inv_logV)
{
    const int row  = blockIdx.x;
    const int tid  = threadIdx.x;
    const int lane = tid & 31;
    const float* p = lf + (size_t)row * (size_t)V;

    __shared__ float rbuf[8];
    __shared__ OS swarp[8];
    __shared__ unsigned hist[256];
    __shared__ unsigned suf[257];
    __shared__ unsigned s_prefix;
    __shared__ int s_rank;
    __shared__ int s_last;
    __shared__ float s_lt;

    // prefetch target logit before the stream evicts the line
    if (tid == 0) s_lt = __ldg(p + __ldg(tf + row));

    // ---- phase 1: per-row streaming stats ----
    // exact top-2 in (m1,m2); exp sums (s0,s1,t0,t1) relative to base bm
    // (kept == m1 after every 8-element group); b2 = bm * log2e.
    float m1 = -INFINITY, m2 = -INFINITY;
    float bm = -INFINITY, b2 = -INFINITY;
    float s0 = 0.f, s1 = 0.f, t0 = 0.f, t1 = 0.f;

    #define TOP2(x) { float lo_ = fminf((x), m1); m1 = fmaxf((x), m1); m2 = fmaxf(m2, lo_); }
    #define RESCALE() if (m1 > bm) { \
        float nb2_ = m1 * LOG2E; \
        float sc_  = ex2f(b2 - nb2_); \
        s0 *= sc_; s1 *= sc_; t0 *= sc_; t1 *= sc_; \
        bm = m1; b2 = nb2_; }
    #define EXP4(v) { float e_; \
        e_ = ex2f(fmaf((v).x, LOG2E, -b2)); s0 += e_; t0 = fmaf(e_, (v).x, t0); \
        e_ = ex2f(fmaf((v).y, LOG2E, -b2)); s1 += e_; t1 = fmaf(e_, (v).y, t1); \
        e_ = ex2f(fmaf((v).z, LOG2E, -b2)); s0 += e_; t0 = fmaf(e_, (v).z, t0); \
        e_ = ex2f(fmaf((v).w, LOG2E, -b2)); s1 += e_; t1 = fmaf(e_, (v).w, t1); }

    if (((V & 3) == 0) && ((((uintptr_t)p) & 15u) == 0)) {
        const int V4 = V >> 2;
        const float4* p4 = reinterpret_cast<const float4*>(p);
        const int pairs = V4 >> 9;          // iterations of 512 float4s (2/thread)
        int i = tid;
        if (pairs > 0) {
            float4 c0 = __ldcs(p4 + i);
            float4 c1 = __ldcs(p4 + i + 256);
            for (int it = 1; it < pairs; it++) {
                int nx = i + 512;
                float4 n0 = __ldcs(p4 + nx);        // prefetch next pair:
                float4 n1 = __ldcs(p4 + nx + 256);  // 4 LDGs in flight during body
                TOP2(c0.x); TOP2(c0.y); TOP2(c0.z); TOP2(c0.w);
                TOP2(c1.x); TOP2(c1.y); TOP2(c1.z); TOP2(c1.w);
                RESCALE();
                EXP4(c0);
                EXP4(c1);
                c0 = n0; c1 = n1; i = nx;
            }
            TOP2(c0.x); TOP2(c0.y); TOP2(c0.z); TOP2(c0.w);
            TOP2(c1.x); TOP2(c1.y); TOP2(c1.z); TOP2(c1.w);
            RESCALE();
            EXP4(c0);
            EXP4(c1);
            i += 512;
        }
        // tail: remaining float4s (V4 % 512)
        for (; i < V4; i += 256) {
            float4 a = __ldcs(p4 + i);
            TOP2(a.x); TOP2(a.y); TOP2(a.z); TOP2(a.w);
            RESCALE();
            EXP4(a);
        }
    } else {
        for (int i = tid; i < V; i += 256) {
            float x = p[i];
            TOP2(x);
            RESCALE();
            float e = ex2f(fmaf(x, LOG2E, -b2));
            s0 += e; t0 = fmaf(e, x, t0);
        }
    }
    #undef TOP2
    #undef RESCALE
    #undef EXP4

    OS st;
    st.m1 = m1; st.m2 = m2; st.s = s0 + s1; st.t = t0 + t1;

    #pragma unroll
    for (int off = 16; off; off >>= 1) {
        OS o;
        o.m1 = __shfl_xor_sync(0xffffffffu, st.m1, off);
        o.m2 = __shfl_xor_sync(0xffffffffu, st.m2, off);
        o.s  = __shfl_xor_sync(0xffffffffu, st.s,  off);
        o.t  = __shfl_xor_sync(0xffffffffu, st.t,  off);
        os_merge(st, o);
    }
    if (lane == 0) swarp[tid >> 5] = st;
    __syncthreads();

    if (tid == 0) {
        #pragma unroll
        for (int w = 1; w < 8; w++) os_merge(st, swarp[w]);

        float logs = __logf(st.s);
        float logZ = st.m1 + logs;
        float ce   = logZ - s_lt;
        float ent  = logZ - st.t / st.s;
        float conf = 1.f / st.s;                    // p1
        float p2   = __expf(st.m2 - st.m1) * conf;  // p2
        float margin = conf - p2;

        g_ce[row]   = ce;
        g_conf[row] = conf;
        g_part[row] = ent * inv_logV + 1.f - margin;

        __threadfence();
        unsigned prev = atomicAdd(&g_done, 1u);
        s_last = (prev == (unsigned)(N - 1)) ? 1 : 0;
    }
    __syncthreads();
    if (!s_last) return;

    // ---- phase 2: finalize (single surviving block) ----
    __threadfence();

    float mce = -INFINITY, sconf = 0.f;
    for (int i = tid; i < N; i += 256) {
        mce = fmaxf(mce, __ldcg(&g_ce[i]));
        sconf += __ldcg(&g_conf[i]);
    }
    float maxce   = blk_max(mce, rbuf);
    float sumconf = blk_sum(sconf, rbuf);

    float invm = 1.f / (maxce + 1e-6f);
    for (int i = tid; i < N; i += 256) {
        float d = (__ldcg(&g_part[i]) + __ldcg(&g_ce[i]) * invm) * (1.f / 3.f);
        g_key[i] = f2key(d);
    }

    if (tid == 0) {
        int   step     = *step_ptr;
        float progress = fminf(1.f, (float)step * (1.f / 1000.f));
        float base_rat = 1.f - progress * (1.f - 0.25f);
        float avg_conf = sumconf / (float)N;
        float ratio    = base_rat * (1.f + 0.5f * (0.5f - avg_conf) * 2.f);
        ratio = fminf(fmaxf(ratio, 0.01f), 1.f);
        int k = (int)rintf(ratio * (float)N);       // round-half-even == jnp.round
        k = min(max(k, 1), N);
        s_rank = k;
        s_prefix = 0u;
    }
    __syncthreads();

    const int Npad = (N + 255) & ~255;

    #pragma unroll
    for (int pass = 0; pass < 4; pass++) {
        const int shift = 24 - pass * 8;
        const unsigned himask = (pass == 0) ? 0u : (0xFFFFFFFFu << (32 - pass * 8));
        hist[tid] = 0u;
        __syncthreads();
        unsigned prefix = s_prefix;

        for (int i = tid; i < Npad; i += 256) {
            int digit = -1;
            if (i < N) {
                unsigned key = g_key[i];
                if ((key & himask) == prefix) digit = (int)((key >> shift) & 255u);
            }
            unsigned m = __match_any_sync(0xffffffffu, digit);
            int leader = __ffs(m) - 1;
            if (lane == leader && digit >= 0)
                atomicAdd(&hist[digit], (unsigned)__popc(m));
        }
        __syncthreads();

        suf[tid] = hist[tid];
        __syncthreads();
        #pragma unroll
        for (int off = 1; off < 256; off <<= 1) {
            unsigned add = (tid + off < 256) ? suf[tid + off] : 0u;
            __syncthreads();
            suf[tid] += add;
            __syncthreads();
        }

        int r = s_rank;
        unsigned here  = suf[tid];
        unsigned above = (tid == 255) ? 0u : suf[tid + 1];
        if ((int)here >= r && (int)above < r) {
            s_prefix = prefix | ((unsigned)tid << shift);
            s_rank = r - (int)above;
        }
        __syncthreads();
    }
    unsigned thr_key = s_prefix;   // exact k-th largest difficulty key

    float sce = 0.f, cnt = 0.f;
    for (int i = tid; i < N; i += 256) {
        if (g_key[i] >= thr_key) { sce += __ldcg(&g_ce[i]); cnt += 1.f; }
    }
    sce = blk_sum(sce, rbuf);
    cnt = blk_sum(cnt, rbuf);
    if (tid == 0) {
        out[0] = sce / fmaxf(cnt, 1.f);
        g_done = 0;               // reset for next graph replay
    }
}

// ---------------------------------------------------------------------------
extern "C" void kernel_launch(void* const* d_in, const int* in_sizes, int n_in,
                              void* d_out, int out_size) {
    const float* lf   = (const float*)d_in[0];   // logits (B,S,V) fp32
    const int*   tf   = (const int*)d_in[1];     // targets (B,S) int32
    const int*   step = (const int*)d_in[2];     // step_count scalar int32

    int N = in_sizes[1];                 // B*S = 8192
    int V = in_sizes[0] / N;             // 32000
    if (N > MAXN) N = MAXN;

    float inv_logV = 1.f / logf((float)V);

    cggr_kernel<<<N, 256>>>(lf, tf, step, (float*)d_out, V, N, inv_logV);
}